// round 1
// baseline (speedup 1.0000x reference)
#include <cuda_runtime.h>

#define N_ 64
#define C_ 128
#define S_ 3600
#define K_ 64
#define TSA 60            // pixels per CTA in kernel A
#define NCHUNK 6
#define CHUNK (S_ / NCHUNK)   // 600
#define TS2 40            // s-tile in kernel B (600 = 15*40)

// ---------------- scratch (static device allocations are allowed) -------------
__device__ float g_a[(size_t)N_ * K_ * S_];           // softmax assignments  (~59 MB)
__device__ float g_rnorm[N_ * S_];                    // per-pixel 1/max(||x||,eps)
__device__ float g_vpart[(size_t)N_ * NCHUNK * K_ * C_];
__device__ float g_asum[N_ * NCHUNK * K_];
__device__ float g_rowss[N_ * K_];

// Kernel A shared layout (dynamic, ~83.7 KB)
#define WT_ELE (C_ * 68)      // wt[c*68 + k]   (transposed conv_w)
#define XS_ELE (C_ * 64)      // xs[c*64 + j]   (x tile, cols 60..63 zero)
#define LS_ELE (K_ * 61)      // ls[k*61 + j]   (logits, then exp values)
#define SMEM_A_FLOATS (WT_ELE + XS_ELE + LS_ELE + 64 + 64)
#define SMEM_A_BYTES (SMEM_A_FLOATS * 4)

// ============================ Kernel A =======================================
// normalize (fold as scalar) + logits GEMM + softmax -> g_a, g_rnorm
__global__ __launch_bounds__(256) void kA(const float* __restrict__ x,
                                          const float* __restrict__ w) {
    extern __shared__ float smem[];
    float* wt   = smem;                 // [C][68]
    float* xs   = wt + WT_ELE;          // [C][64]
    float* ls   = xs + XS_ELE;          // [K][61]
    float* rn   = ls + LS_ELE;          // [64]
    float* rinv = rn + 64;              // [64]

    const int n   = blockIdx.y;
    const int s0  = blockIdx.x * TSA;
    const int tid = threadIdx.x;

    // load conv_w transposed: wt[c][k]
    for (int i = tid; i < K_ * C_; i += 256) {
        int k = i >> 7, c = i & 127;
        wt[c * 68 + k] = w[i];
    }
    // load x tile [C][64], zero-pad cols 60..63
    const float* xb = x + (size_t)n * C_ * S_ + s0;
    for (int i = tid; i < C_ * 64; i += 256) {
        int c = i >> 6, j = i & 63;
        xs[i] = (j < TSA) ? xb[c * S_ + j] : 0.f;
    }
    __syncthreads();

    // per-pixel rnorm: 4 threads per pixel (all 256 threads run; p>=60 discarded)
    {
        int p = tid >> 2, q = tid & 3;
        float ss = 0.f;
        for (int c = q; c < C_; c += 4) {
            float v = xs[c * 64 + p];
            ss += v * v;
        }
        ss += __shfl_xor_sync(0xffffffffu, ss, 1);
        ss += __shfl_xor_sync(0xffffffffu, ss, 2);
        if (q == 0 && p < TSA) {
            float r = 1.0f / fmaxf(sqrtf(ss), 1e-12f);
            rn[p] = r;
            g_rnorm[n * S_ + s0 + p] = r;
        }
    }
    __syncthreads();

    // logits GEMM: ls[k][s] = sum_c wt[c][k] * xs[c][s]; 4k x 4s per thread
    {
        const int tk = tid & 15;     // k0 = 4*tk
        const int ts = tid >> 4;     // s0t = 4*ts, active for ts < 15
        if (ts < 15) {
            float a00=0,a01=0,a02=0,a03=0, a10=0,a11=0,a12=0,a13=0;
            float a20=0,a21=0,a22=0,a23=0, a30=0,a31=0,a32=0,a33=0;
            #pragma unroll 4
            for (int c = 0; c < C_; c++) {
                float4 wv = *(const float4*)(wt + c * 68 + 4 * tk);
                float4 xv = *(const float4*)(xs + c * 64 + 4 * ts);
                a00 = fmaf(wv.x, xv.x, a00); a01 = fmaf(wv.x, xv.y, a01);
                a02 = fmaf(wv.x, xv.z, a02); a03 = fmaf(wv.x, xv.w, a03);
                a10 = fmaf(wv.y, xv.x, a10); a11 = fmaf(wv.y, xv.y, a11);
                a12 = fmaf(wv.y, xv.z, a12); a13 = fmaf(wv.y, xv.w, a13);
                a20 = fmaf(wv.z, xv.x, a20); a21 = fmaf(wv.z, xv.y, a21);
                a22 = fmaf(wv.z, xv.z, a22); a23 = fmaf(wv.z, xv.w, a23);
                a30 = fmaf(wv.w, xv.x, a30); a31 = fmaf(wv.w, xv.y, a31);
                a32 = fmaf(wv.w, xv.z, a32); a33 = fmaf(wv.w, xv.w, a33);
            }
            int k0 = 4 * tk, j0 = 4 * ts;
            ls[(k0+0)*61 + j0+0]=a00; ls[(k0+0)*61 + j0+1]=a01; ls[(k0+0)*61 + j0+2]=a02; ls[(k0+0)*61 + j0+3]=a03;
            ls[(k0+1)*61 + j0+0]=a10; ls[(k0+1)*61 + j0+1]=a11; ls[(k0+1)*61 + j0+2]=a12; ls[(k0+1)*61 + j0+3]=a13;
            ls[(k0+2)*61 + j0+0]=a20; ls[(k0+2)*61 + j0+1]=a21; ls[(k0+2)*61 + j0+2]=a22; ls[(k0+2)*61 + j0+3]=a23;
            ls[(k0+3)*61 + j0+0]=a30; ls[(k0+3)*61 + j0+1]=a31; ls[(k0+3)*61 + j0+2]=a32; ls[(k0+3)*61 + j0+3]=a33;
        }
    }
    __syncthreads();

    // softmax over K per pixel (scale logits by rnorm first). 4 threads/pixel.
    {
        int p = tid >> 2, q = tid & 3;
        float r = (p < TSA) ? rn[p] : 1.f;
        float m = -1e30f;
        if (p < TSA) {
            for (int k = q; k < K_; k += 4) m = fmaxf(m, ls[k * 61 + p] * r);
        }
        m = fmaxf(m, __shfl_xor_sync(0xffffffffu, m, 1));
        m = fmaxf(m, __shfl_xor_sync(0xffffffffu, m, 2));
        float s = 0.f;
        if (p < TSA) {
            for (int k = q; k < K_; k += 4) {
                float e = __expf(ls[k * 61 + p] * r - m);
                s += e;
                ls[k * 61 + p] = e;
            }
        }
        s += __shfl_xor_sync(0xffffffffu, s, 1);
        s += __shfl_xor_sync(0xffffffffu, s, 2);
        if (q == 0 && p < TSA) rinv[p] = 1.0f / s;
    }
    __syncthreads();

    // write a = exp * rinv (coalesced rows of 60)
    float* ga = g_a + ((size_t)n * K_) * S_ + s0;
    for (int i = tid; i < K_ * TSA; i += 256) {
        int k = i / TSA, j = i - k * TSA;
        ga[(size_t)k * S_ + j] = ls[k * 61 + j] * rinv[j];
    }
}

// ============================ Kernel B =======================================
// vlad partials: vpart[n,ch,k,c] = sum_{s in chunk} a[k,s] * x[c,s]*rnorm[s]
// asum[n,ch,k]  = sum_{s in chunk} a[k,s]
__global__ __launch_bounds__(256) void kB(const float* __restrict__ x) {
    __shared__ float as_t[TS2 * 68];    // [s][k]  pad 68
    __shared__ float xs_t[TS2 * 132];   // [s][c]  pad 132

    const int n  = blockIdx.y;
    const int ch = blockIdx.x;
    const int tid = threadIdx.x;
    const int tk = tid & 7;     // k0 = 8*tk
    const int tc = tid >> 3;    // c0 = 4*tc  (tc in [0,32))

    const float* xb  = x + (size_t)n * C_ * S_;
    const float* ab  = g_a + (size_t)n * K_ * S_;
    const float* rnb = g_rnorm + n * S_;

    float acc[8][4];
    #pragma unroll
    for (int i = 0; i < 8; i++)
        #pragma unroll
        for (int j = 0; j < 4; j++) acc[i][j] = 0.f;
    float asum[8];
    #pragma unroll
    for (int i = 0; i < 8; i++) asum[i] = 0.f;

    const int sbase0 = ch * CHUNK;
    for (int t = 0; t < CHUNK / TS2; t++) {
        const int sb = sbase0 + t * TS2;
        __syncthreads();
        // a tile (transposed store)
        for (int i = tid; i < K_ * TS2; i += 256) {
            int k = i / TS2, j = i - k * TS2;
            as_t[j * 68 + k] = ab[(size_t)k * S_ + sb + j];
        }
        // x tile scaled by rnorm (transposed store)
        for (int i = tid; i < C_ * TS2; i += 256) {
            int c = i / TS2, j = i - c * TS2;
            xs_t[j * 132 + c] = xb[(size_t)c * S_ + sb + j] * rnb[sb + j];
        }
        __syncthreads();

        #pragma unroll 2
        for (int s = 0; s < TS2; s++) {
            const float* ap = as_t + s * 68 + 8 * tk;
            float4 a0 = *(const float4*)(ap);
            float4 a1 = *(const float4*)(ap + 4);
            float4 xq = *(const float4*)(xs_t + s * 132 + 4 * tc);
            float av[8] = {a0.x, a0.y, a0.z, a0.w, a1.x, a1.y, a1.z, a1.w};
            float xv[4] = {xq.x, xq.y, xq.z, xq.w};
            if (tc == 0) {
                #pragma unroll
                for (int i = 0; i < 8; i++) asum[i] += av[i];
            }
            #pragma unroll
            for (int i = 0; i < 8; i++)
                #pragma unroll
                for (int j = 0; j < 4; j++)
                    acc[i][j] = fmaf(av[i], xv[j], acc[i][j]);
        }
    }

    // write partials
    float* vp = g_vpart + (((size_t)n * NCHUNK + ch) * K_ + 8 * tk) * C_ + 4 * tc;
    #pragma unroll
    for (int i = 0; i < 8; i++) {
        float4 o = make_float4(acc[i][0], acc[i][1], acc[i][2], acc[i][3]);
        *(float4*)(vp + (size_t)i * C_) = o;
    }
    if (tc == 0) {
        float* ap2 = g_asum + (n * NCHUNK + ch) * K_ + 8 * tk;
        #pragma unroll
        for (int i = 0; i < 8; i++) ap2[i] = asum[i];
    }
}

// ============================ Kernel C1 ======================================
// reduce chunks, subtract asum*centroid, intra-normalize row, store row sumsq
__global__ __launch_bounds__(128) void kC1(const float* __restrict__ cent,
                                           float* __restrict__ out) {
    const int n = blockIdx.y, k = blockIdx.x, c = threadIdx.x;

    float asum = 0.f;
    #pragma unroll
    for (int ch = 0; ch < NCHUNK; ch++)
        asum += g_asum[(n * NCHUNK + ch) * K_ + k];

    float v = 0.f;
    #pragma unroll
    for (int ch = 0; ch < NCHUNK; ch++)
        v += g_vpart[(((size_t)n * NCHUNK + ch) * K_ + k) * C_ + c];
    v -= asum * cent[k * C_ + c];

    float ss = v * v;
    #pragma unroll
    for (int o = 16; o; o >>= 1) ss += __shfl_xor_sync(0xffffffffu, ss, o);
    __shared__ float sred[4];
    if ((c & 31) == 0) sred[c >> 5] = ss;
    __syncthreads();
    float tot = sred[0] + sred[1] + sred[2] + sred[3];

    float nrm = sqrtf(tot);
    float d = fmaxf(nrm, 1e-12f);
    out[((size_t)n * K_ + k) * C_ + c] = v / d;
    if (c == 0) g_rowss[n * K_ + k] = tot / (d * d);
}

// ============================ Kernel C2 ======================================
// global L2 norm per n over the 8192-vector
__global__ __launch_bounds__(256) void kC2(float* __restrict__ out) {
    const int n = blockIdx.x, tid = threadIdx.x;
    __shared__ float sred[2];
    if (tid < 64) {
        float ss = g_rowss[n * 64 + tid];
        #pragma unroll
        for (int o = 16; o; o >>= 1) ss += __shfl_xor_sync(0xffffffffu, ss, o);
        if ((tid & 31) == 0) sred[tid >> 5] = ss;
    }
    __syncthreads();
    float d = fmaxf(sqrtf(sred[0] + sred[1]), 1e-12f);
    float r = 1.0f / d;
    float* o = out + (size_t)n * K_ * C_;
    for (int i = tid; i < K_ * C_; i += 256) o[i] *= r;
}

// ============================ launch =========================================
extern "C" void kernel_launch(void* const* d_in, const int* in_sizes, int n_in,
                              void* d_out, int out_size) {
    const float* x    = (const float*)d_in[0];
    const float* w    = (const float*)d_in[1];
    const float* cent = (const float*)d_in[2];
    float* out = (float*)d_out;

    cudaFuncSetAttribute(kA, cudaFuncAttributeMaxDynamicSharedMemorySize,
                         SMEM_A_BYTES);

    kA<<<dim3(S_ / TSA, N_), 256, SMEM_A_BYTES>>>(x, w);
    kB<<<dim3(NCHUNK, N_), 256>>>(x);
    kC1<<<dim3(K_, N_), 128>>>(cent, out);
    kC2<<<N_, 256>>>(out);
}

// round 6
// speedup vs baseline: 2.0996x; 2.0996x over previous
#include <cuda_runtime.h>
#include <cuda_bf16.h>

#define N_ 64
#define C_ 128
#define S_ 3600
#define K_ 64
#define NT 29              // tiles of 128 pixels
#define SPAD (NT * 128)    // 3712
#define SPLIT 8
#define LDX 136            // bf16 row stride (272B: conflict-free ldmatrix)
#define LDL 65             // fp32 logits row stride (conflict-free softmax)

// ---------------- static device scratch --------------------------------------
__device__ __align__(128) __nv_bfloat16 g_abf[(size_t)N_ * K_ * SPAD]; // [n][k][s]
__device__ float g_rnorm[N_ * SPAD];
__device__ float g_d2part[(size_t)N_ * SPLIT * C_ * K_];               // [n][p][c][k]
__device__ float g_asump[N_ * NT * K_];
__device__ float g_rowss[N_ * K_];

// ---------------- helpers -----------------------------------------------------
__device__ __forceinline__ unsigned smem_u32(const void* p) {
    unsigned a;
    asm("{ .reg .u64 t; cvta.to.shared.u64 t, %1; cvt.u32.u64 %0, t; }"
        : "=r"(a) : "l"(p));
    return a;
}
__device__ __forceinline__ void ldsm4t(unsigned addr, unsigned& r0, unsigned& r1,
                                       unsigned& r2, unsigned& r3) {
    asm volatile("ldmatrix.sync.aligned.m8n8.x4.trans.shared.b16 {%0,%1,%2,%3}, [%4];"
                 : "=r"(r0), "=r"(r1), "=r"(r2), "=r"(r3) : "r"(addr));
}
__device__ __forceinline__ void ldsm4(unsigned addr, unsigned& r0, unsigned& r1,
                                      unsigned& r2, unsigned& r3) {
    asm volatile("ldmatrix.sync.aligned.m8n8.x4.shared.b16 {%0,%1,%2,%3}, [%4];"
                 : "=r"(r0), "=r"(r1), "=r"(r2), "=r"(r3) : "r"(addr));
}
__device__ __forceinline__ void ldsm2(unsigned addr, unsigned& r0, unsigned& r1) {
    asm volatile("ldmatrix.sync.aligned.m8n8.x2.shared.b16 {%0,%1}, [%2];"
                 : "=r"(r0), "=r"(r1) : "r"(addr));
}
__device__ __forceinline__ void mma_bf16(float* d, const unsigned* a, const unsigned* b) {
    asm volatile("mma.sync.aligned.m16n8k16.row.col.f32.bf16.bf16.f32 "
                 "{%0,%1,%2,%3}, {%4,%5,%6,%7}, {%8,%9}, {%0,%1,%2,%3};"
                 : "+f"(d[0]), "+f"(d[1]), "+f"(d[2]), "+f"(d[3])
                 : "r"(a[0]), "r"(a[1]), "r"(a[2]), "r"(a[3]), "r"(b[0]), "r"(b[1]));
}
__device__ __forceinline__ unsigned pack4bf(float a, float b, float c, float d,
                                            unsigned& hi) {
    union { __nv_bfloat16 h[2]; unsigned u; } lo_u, hi_u;
    lo_u.h[0] = __float2bfloat16_rn(a); lo_u.h[1] = __float2bfloat16_rn(b);
    hi_u.h[0] = __float2bfloat16_rn(c); hi_u.h[1] = __float2bfloat16_rn(d);
    hi = hi_u.u;
    return lo_u.u;
}

// ============================ kF1 =============================================
// fused: x->bf16, rnorm, logits HMMA (s x k), softmax, a^T + asum + rnorm out
#define F1_XBF 0
#define F1_WBF (F1_XBF + C_ * LDX * 2)          // 34816
#define F1_LS  (F1_WBF + K_ * LDX * 2)          // 52224
#define F1_AST (F1_LS + 128 * LDL * 4)          // 85504
#define F1_RN  (F1_AST + K_ * LDX * 2)          // 102912
#define F1_ASU (F1_RN + 512)                    // 103424
#define F1_BYTES (F1_ASU + 512)                 // 103936
__global__ __launch_bounds__(256) void kF1(const float* __restrict__ x,
                                           const float* __restrict__ w) {
    extern __shared__ char smc[];
    __nv_bfloat16* xbf = (__nv_bfloat16*)(smc + F1_XBF);  // [128 c][LDX s]
    __nv_bfloat16* wbf = (__nv_bfloat16*)(smc + F1_WBF);  // [64 k][LDX c]
    float* ls   = (float*)(smc + F1_LS);                  // [128 s][LDL k]
    __nv_bfloat16* ast = (__nv_bfloat16*)(smc + F1_AST);  // [64 k][LDX s]
    float* rn   = (float*)(smc + F1_RN);                  // [128]
    float* asums = (float*)(smc + F1_ASU);                // [128]

    const int tid = threadIdx.x, lane = tid & 31, wid = tid >> 5;
    const int n = blockIdx.y, t0 = blockIdx.x, s0 = t0 * 128;

    // --- load x tile [c][s0..s0+127] fp32 -> bf16 smem (unscaled) ---
    {
        const int c = tid >> 1, h = tid & 1;
        const float* xr = x + ((size_t)n * C_ + c) * S_;
        #pragma unroll
        for (int q = 0; q < 16; q++) {
            int s = s0 + h * 64 + 4 * q;
            float4 v = make_float4(0.f, 0.f, 0.f, 0.f);
            if (s + 4 <= S_) v = *(const float4*)(xr + s);
            unsigned hi, lo = pack4bf(v.x, v.y, v.z, v.w, hi);
            uint2 pv = make_uint2(lo, hi);
            *(uint2*)(xbf + c * LDX + h * 64 + 4 * q) = pv;
        }
    }
    // --- load w [k][c] fp32 -> bf16 smem ---
    {
        const int k = tid >> 2, qq = tid & 3;
        const float* wr = w + k * C_;
        #pragma unroll
        for (int j = 0; j < 8; j++) {
            int c = qq * 32 + 4 * j;
            float4 v = *(const float4*)(wr + c);
            unsigned hi, lo = pack4bf(v.x, v.y, v.z, v.w, hi);
            *(uint2*)(wbf + k * LDX + c) = make_uint2(lo, hi);
        }
    }
    __syncthreads();

    // --- rnorm per pixel from bf16 tile ---
    if (tid < 128) {
        float ss = 0.f;
        #pragma unroll 8
        for (int c = 0; c < C_; c++) {
            float v = __bfloat162float(xbf[c * LDX + tid]);
            ss = fmaf(v, v, ss);
        }
        float r = (s0 + tid < S_) ? (1.0f / fmaxf(sqrtf(ss), 1e-12f)) : 0.f;
        rn[tid] = r;
        g_rnorm[n * SPAD + s0 + tid] = r;
    }
    __syncthreads();

    // --- scale xbf in place by rn[s] ---
    {
        unsigned* xw = (unsigned*)xbf;
        for (int i = tid; i < 128 * 64; i += 256) {
            int c = i >> 6, sw = i & 63;
            unsigned v = xw[c * (LDX / 2) + sw];
            union { __nv_bfloat16 h[2]; unsigned u; } u;
            u.u = v;
            u.h[0] = __float2bfloat16_rn(__bfloat162float(u.h[0]) * rn[2 * sw]);
            u.h[1] = __float2bfloat16_rn(__bfloat162float(u.h[1]) * rn[2 * sw + 1]);
            xw[c * (LDX / 2) + sw] = u.u;
        }
    }
    __syncthreads();

    // --- HMMA: logits[s][k] = xn[s][c] . w[k][c] ---
    const unsigned xb_u = smem_u32(xbf), wb_u = smem_u32(wbf);
    const int msb = (wid & 3) * 32, ksb = (wid >> 2) * 32;
    float acc[2][4][4];
    #pragma unroll
    for (int i = 0; i < 2; i++)
        #pragma unroll
        for (int j = 0; j < 4; j++)
            #pragma unroll
            for (int q = 0; q < 4; q++) acc[i][j][q] = 0.f;

    const int lb = lane >> 3, lr = lane & 7, lb2 = (lane >> 3) & 1;
    #pragma unroll
    for (int kc = 0; kc < 8; kc++) {
        const int c0 = kc * 16;
        unsigned af[2][4], bfr[4][2];
        #pragma unroll
        for (int mt = 0; mt < 2; mt++) {
            unsigned addr = xb_u +
                ((unsigned)((c0 + ((lb & 2) ? 8 : 0) + lr) * LDX +
                            (msb + 16 * mt) + ((lb & 1) ? 8 : 0)) << 1);
            ldsm4t(addr, af[mt][0], af[mt][1], af[mt][2], af[mt][3]);
        }
        #pragma unroll
        for (int nt = 0; nt < 4; nt++) {
            unsigned addr = wb_u +
                ((unsigned)((ksb + 8 * nt + lr) * LDX + c0 + lb2 * 8) << 1);
            ldsm2(addr, bfr[nt][0], bfr[nt][1]);
        }
        #pragma unroll
        for (int mt = 0; mt < 2; mt++)
            #pragma unroll
            for (int nt = 0; nt < 4; nt++) mma_bf16(acc[mt][nt], af[mt], bfr[nt]);
    }
    // write logits to ls
    #pragma unroll
    for (int mt = 0; mt < 2; mt++)
        #pragma unroll
        for (int nt = 0; nt < 4; nt++) {
            int row = msb + 16 * mt + (lane >> 2);
            int col = ksb + 8 * nt + 2 * (lane & 3);
            ls[row * LDL + col]       = acc[mt][nt][0];
            ls[row * LDL + col + 1]   = acc[mt][nt][1];
            ls[(row + 8) * LDL + col]     = acc[mt][nt][2];
            ls[(row + 8) * LDL + col + 1] = acc[mt][nt][3];
        }
    __syncthreads();

    // --- softmax per pixel ---
    if (tid < 128) {
        const int s = tid;
        const bool valid = (s0 + s) < S_;
        float m = -1e30f;
        #pragma unroll 8
        for (int k = 0; k < 64; k++) m = fmaxf(m, ls[s * LDL + k]);
        float sum = 0.f;
        #pragma unroll 8
        for (int k = 0; k < 64; k++) {
            float e = __expf(ls[s * LDL + k] - m);
            sum += e;
            ls[s * LDL + k] = e;
        }
        float rinv = valid ? (1.0f / sum) : 0.f;
        #pragma unroll 8
        for (int k = 0; k < 64; k++)
            ast[k * LDX + s] = __float2bfloat16_rn(ls[s * LDL + k] * rinv);
    }
    __syncthreads();

    // --- asum partials (sum of stored bf16 a) ---
    if (tid < 128) {
        int k = tid & 63, h = tid >> 6;
        float ssum = 0.f;
        #pragma unroll 8
        for (int u = 0; u < 64; u++) ssum += __bfloat162float(ast[k * LDX + h * 64 + u]);
        asums[tid] = ssum;
    }
    __syncthreads();
    if (tid < 64) g_asump[(n * NT + t0) * K_ + tid] = asums[tid] + asums[tid + 64];

    // --- store a[k][s] bf16 (coalesced) ---
    for (int i = tid; i < K_ * 16; i += 256) {
        int k = i >> 4, g = i & 15;
        uint4 v = *(const uint4*)(ast + k * LDX + 8 * g);
        *(uint4*)(g_abf + (size_t)(n * K_ + k) * SPAD + s0 + 8 * g) = v;
    }
}

// ============================ kF2 =============================================
// vlad partials [c][k] += xn[c][s] . a[k][s] over s-tiles (fused x read+scale)
#define F2_XBF 0
#define F2_AS  (F2_XBF + C_ * LDX * 2)   // 34816
#define F2_RN  (F2_AS + K_ * LDX * 2)    // 52224
#define F2_BYTES (F2_RN + 512)           // 52736
__global__ __launch_bounds__(256) void kF2(const float* __restrict__ x) {
    extern __shared__ char smc[];
    __nv_bfloat16* xbf = (__nv_bfloat16*)(smc + F2_XBF);  // [128 c][LDX s]
    __nv_bfloat16* as  = (__nv_bfloat16*)(smc + F2_AS);   // [64 k][LDX s]
    float* rn = (float*)(smc + F2_RN);                    // [128]

    const int tid = threadIdx.x, lane = tid & 31, wid = tid >> 5;
    const int n = blockIdx.y, p = blockIdx.x;
    const int tbeg = p * 4;
    const int tend = min(tbeg + 4, NT);

    const unsigned xb_u = smem_u32(xbf), as_u = smem_u32(as);
    const int csb = (wid & 3) * 32, ksb = (wid >> 2) * 32;
    const int lb = lane >> 3, lr = lane & 7, lb2 = (lane >> 3) & 1;

    float acc[2][4][4];
    #pragma unroll
    for (int i = 0; i < 2; i++)
        #pragma unroll
        for (int j = 0; j < 4; j++)
            #pragma unroll
            for (int q = 0; q < 4; q++) acc[i][j][q] = 0.f;

    for (int t = tbeg; t < tend; t++) {
        const int s0 = t * 128;
        __syncthreads();   // smem free from previous iteration
        if (tid < 128) rn[tid] = g_rnorm[n * SPAD + s0 + tid];
        // a tile [k][s]: full 128-wide rows (4 slices of 8 bf16 per thread)
        {
            const int k = tid >> 2, q = tid & 3;
            const __nv_bfloat16* src = g_abf + (size_t)(n * K_ + k) * SPAD + s0;
            #pragma unroll
            for (int j = 0; j < 4; j++) {
                int sl = 8 * q + 32 * j;
                *(uint4*)(as + k * LDX + sl) = *(const uint4*)(src + sl);
            }
        }
        __syncthreads();   // rn visible
        // x tile -> scaled bf16
        {
            const int c = tid >> 1, h = tid & 1;
            const float* xr = x + ((size_t)n * C_ + c) * S_;
            #pragma unroll
            for (int q = 0; q < 16; q++) {
                int sl = h * 64 + 4 * q, s = s0 + sl;
                float4 v = make_float4(0.f, 0.f, 0.f, 0.f);
                if (s + 4 <= S_) v = *(const float4*)(xr + s);
                unsigned hi, lo = pack4bf(v.x * rn[sl], v.y * rn[sl + 1],
                                          v.z * rn[sl + 2], v.w * rn[sl + 3], hi);
                *(uint2*)(xbf + c * LDX + sl) = make_uint2(lo, hi);
            }
        }
        __syncthreads();   // tiles ready

        #pragma unroll
        for (int ks = 0; ks < 8; ks++) {
            const int sst = ks * 16;
            unsigned af[2][4], bfr[4][2];
            #pragma unroll
            for (int mt = 0; mt < 2; mt++) {
                unsigned addr = xb_u +
                    ((unsigned)((csb + 16 * mt + (lb & 1) * 8 + lr) * LDX +
                                sst + ((lb & 2) ? 8 : 0)) << 1);
                ldsm4(addr, af[mt][0], af[mt][1], af[mt][2], af[mt][3]);
            }
            #pragma unroll
            for (int nt = 0; nt < 4; nt++) {
                unsigned addr = as_u +
                    ((unsigned)((ksb + 8 * nt + lr) * LDX + sst + lb2 * 8) << 1);
                ldsm2(addr, bfr[nt][0], bfr[nt][1]);
            }
            #pragma unroll
            for (int mt = 0; mt < 2; mt++)
                #pragma unroll
                for (int nt = 0; nt < 4; nt++) mma_bf16(acc[mt][nt], af[mt], bfr[nt]);
        }
    }

    // write partials [c][k]
    float* dst = g_d2part + (size_t)(n * SPLIT + p) * C_ * K_;
    #pragma unroll
    for (int mt = 0; mt < 2; mt++)
        #pragma unroll
        for (int nt = 0; nt < 4; nt++) {
            int row = csb + 16 * mt + (lane >> 2);
            int col = ksb + 8 * nt + 2 * (lane & 3);
            *(float2*)(dst + row * K_ + col) = make_float2(acc[mt][nt][0], acc[mt][nt][1]);
            *(float2*)(dst + (row + 8) * K_ + col) = make_float2(acc[mt][nt][2], acc[mt][nt][3]);
        }
}

// ============================ kC1 / kC2 ======================================
__global__ __launch_bounds__(128) void kC1(const float* __restrict__ cent,
                                           float* __restrict__ out) {
    const int n = blockIdx.y, k = blockIdx.x, c = threadIdx.x;
    float asum = 0.f;
    #pragma unroll 1
    for (int t = 0; t < NT; t++) asum += g_asump[(n * NT + t) * K_ + k];
    float v = 0.f;
    #pragma unroll
    for (int p = 0; p < SPLIT; p++)
        v += g_d2part[(size_t)(n * SPLIT + p) * C_ * K_ + c * K_ + k];
    v -= asum * cent[k * C_ + c];

    float ss = v * v;
    #pragma unroll
    for (int o = 16; o; o >>= 1) ss += __shfl_xor_sync(0xffffffffu, ss, o);
    __shared__ float sred[4];
    if ((c & 31) == 0) sred[c >> 5] = ss;
    __syncthreads();
    float tot = sred[0] + sred[1] + sred[2] + sred[3];
    float d = fmaxf(sqrtf(tot), 1e-12f);
    out[((size_t)n * K_ + k) * C_ + c] = v / d;
    if (c == 0) g_rowss[n * K_ + k] = tot / (d * d);
}

__global__ __launch_bounds__(256) void kC2(float* __restrict__ out) {
    const int n = blockIdx.x, tid = threadIdx.x;
    __shared__ float sred[2];
    if (tid < 64) {
        float ss = g_rowss[n * 64 + tid];
        #pragma unroll
        for (int o = 16; o; o >>= 1) ss += __shfl_xor_sync(0xffffffffu, ss, o);
        if ((tid & 31) == 0) sred[tid >> 5] = ss;
    }
    __syncthreads();
    float d = fmaxf(sqrtf(sred[0] + sred[1]), 1e-12f);
    float r = 1.0f / d;
    float* o = out + (size_t)n * K_ * C_;
    for (int i = tid; i < K_ * C_; i += 256) o[i] *= r;
}

// ============================ launch =========================================
extern "C" void kernel_launch(void* const* d_in, const int* in_sizes, int n_in,
                              void* d_out, int out_size) {
    const float* x    = (const float*)d_in[0];
    const float* w    = (const float*)d_in[1];
    const float* cent = (const float*)d_in[2];
    float* out = (float*)d_out;

    cudaFuncSetAttribute(kF1, cudaFuncAttributeMaxDynamicSharedMemorySize, F1_BYTES);
    cudaFuncSetAttribute(kF2, cudaFuncAttributeMaxDynamicSharedMemorySize, F2_BYTES);

    kF1<<<dim3(NT, N_), 256, F1_BYTES>>>(x, w);
    kF2<<<dim3(SPLIT, N_), 256, F2_BYTES>>>(x);
    kC1<<<dim3(K_, N_), 128>>>(cent, out);
    kC2<<<N_, 256>>>(out);
}

// round 9
// speedup vs baseline: 2.1205x; 1.0100x over previous
#include <cuda_runtime.h>
#include <cuda_bf16.h>

#define N_ 64
#define C_ 128
#define S_ 3600
#define K_ 64
#define NT 29              // tiles of 128 pixels
#define SPAD (NT * 128)    // 3712
#define SPLIT 8
#define LDX 136            // bf16 row stride (272B: conflict-free ldmatrix)
#define LDL 65             // fp32 logits row stride (conflict-free softmax)

// ---------------- static device scratch --------------------------------------
__device__ __align__(128) __nv_bfloat16 g_abf[(size_t)N_ * K_ * SPAD]; // [n][k][s]
__device__ float g_rnorm[N_ * SPAD];
__device__ float g_d2part[(size_t)N_ * SPLIT * C_ * K_];               // [n][p][c][k]
__device__ float g_asump[N_ * NT * K_];
__device__ float g_rowss[N_ * K_];

// ---------------- helpers -----------------------------------------------------
__device__ __forceinline__ unsigned smem_u32(const void* p) {
    unsigned a;
    asm("{ .reg .u64 t; cvta.to.shared.u64 t, %1; cvt.u32.u64 %0, t; }"
        : "=r"(a) : "l"(p));
    return a;
}
__device__ __forceinline__ void ldsm4t(unsigned addr, unsigned& r0, unsigned& r1,
                                       unsigned& r2, unsigned& r3) {
    asm volatile("ldmatrix.sync.aligned.m8n8.x4.trans.shared.b16 {%0,%1,%2,%3}, [%4];"
                 : "=r"(r0), "=r"(r1), "=r"(r2), "=r"(r3) : "r"(addr));
}
__device__ __forceinline__ void ldsm4(unsigned addr, unsigned& r0, unsigned& r1,
                                      unsigned& r2, unsigned& r3) {
    asm volatile("ldmatrix.sync.aligned.m8n8.x4.shared.b16 {%0,%1,%2,%3}, [%4];"
                 : "=r"(r0), "=r"(r1), "=r"(r2), "=r"(r3) : "r"(addr));
}
__device__ __forceinline__ void ldsm2(unsigned addr, unsigned& r0, unsigned& r1) {
    asm volatile("ldmatrix.sync.aligned.m8n8.x2.shared.b16 {%0,%1}, [%2];"
                 : "=r"(r0), "=r"(r1) : "r"(addr));
}
__device__ __forceinline__ void mma_bf16(float* d, const unsigned* a, const unsigned* b) {
    asm volatile("mma.sync.aligned.m16n8k16.row.col.f32.bf16.bf16.f32 "
                 "{%0,%1,%2,%3}, {%4,%5,%6,%7}, {%8,%9}, {%0,%1,%2,%3};"
                 : "+f"(d[0]), "+f"(d[1]), "+f"(d[2]), "+f"(d[3])
                 : "r"(a[0]), "r"(a[1]), "r"(a[2]), "r"(a[3]), "r"(b[0]), "r"(b[1]));
}
__device__ __forceinline__ unsigned pack4bf(float a, float b, float c, float d,
                                            unsigned& hi) {
    union { __nv_bfloat16 h[2]; unsigned u; } lo_u, hi_u;
    lo_u.h[0] = __float2bfloat16_rn(a); lo_u.h[1] = __float2bfloat16_rn(b);
    hi_u.h[0] = __float2bfloat16_rn(c); hi_u.h[1] = __float2bfloat16_rn(d);
    hi = hi_u.u;
    return lo_u.u;
}
// exp(x) on the FMA/ALU pipes (no MUFU). rel err ~2e-6. x expected <= 0.
__device__ __forceinline__ float fexp(float x) {
    x = fmaxf(x, -60.0f);
    float t = fmaf(x, 1.44269504089f, 12582912.0f);   // 2^23*1.5 magic round
    int ei = __float_as_int(t) - 0x4B400000;          // integer part (signed)
    float i = t - 12582912.0f;
    float f = fmaf(x, 1.44269504089f, -i);            // frac in [-0.5,0.5]
    float p = 1.33335581e-3f;
    p = fmaf(p, f, 9.61812910e-3f);
    p = fmaf(p, f, 5.55041087e-2f);
    p = fmaf(p, f, 2.40226507e-1f);
    p = fmaf(p, f, 6.93147181e-1f);
    p = fmaf(p, f, 1.0f);                             // 2^f
    return __int_as_float(__float_as_int(p) + (ei << 23));
}

// ============================ kF1 =============================================
// fused: x->bf16, rnorm, logits HMMA (s x k), softmax, a^T + asum + rnorm out
#define F1_XBF 0
#define F1_WBF (F1_XBF + C_ * LDX * 2)          // 34816
#define F1_LS  (F1_WBF + K_ * LDX * 2)          // 52224
#define F1_AST (F1_LS + 128 * LDL * 4)          // 85504
#define F1_RN  (F1_AST + K_ * LDX * 2)          // 102912
#define F1_ASU (F1_RN + 512)                    // 103424
#define F1_BYTES (F1_ASU + 512)                 // 103936
__global__ __launch_bounds__(256) void kF1(const float* __restrict__ x,
                                           const float* __restrict__ w) {
    extern __shared__ char smc[];
    __nv_bfloat16* xbf = (__nv_bfloat16*)(smc + F1_XBF);  // [128 c][LDX s]
    __nv_bfloat16* wbf = (__nv_bfloat16*)(smc + F1_WBF);  // [64 k][LDX c]
    float* ls   = (float*)(smc + F1_LS);                  // [128 s][LDL k]
    __nv_bfloat16* ast = (__nv_bfloat16*)(smc + F1_AST);  // [64 k][LDX s]
    float* rn   = (float*)(smc + F1_RN);                  // [128]
    float* asums = (float*)(smc + F1_ASU);                // [128]

    const int tid = threadIdx.x, lane = tid & 31, wid = tid >> 5;
    const int n = blockIdx.y, t0 = blockIdx.x, s0 = t0 * 128;

    // --- load x tile [c][s0..s0+127] fp32 -> bf16 smem (unscaled) ---
    {
        const int c = tid >> 1, h = tid & 1;
        const float* xr = x + ((size_t)n * C_ + c) * S_;
        #pragma unroll
        for (int q = 0; q < 16; q++) {
            int s = s0 + h * 64 + 4 * q;
            float4 v = make_float4(0.f, 0.f, 0.f, 0.f);
            if (s + 4 <= S_) v = *(const float4*)(xr + s);
            unsigned hi, lo = pack4bf(v.x, v.y, v.z, v.w, hi);
            uint2 pv = make_uint2(lo, hi);
            *(uint2*)(xbf + c * LDX + h * 64 + 4 * q) = pv;
        }
    }
    // --- load w [k][c] fp32 -> bf16 smem ---
    {
        const int k = tid >> 2, qq = tid & 3;
        const float* wr = w + k * C_;
        #pragma unroll
        for (int j = 0; j < 8; j++) {
            int c = qq * 32 + 4 * j;
            float4 v = *(const float4*)(wr + c);
            unsigned hi, lo = pack4bf(v.x, v.y, v.z, v.w, hi);
            *(uint2*)(wbf + k * LDX + c) = make_uint2(lo, hi);
        }
    }
    __syncthreads();

    // --- rnorm per pixel from bf16 tile ---
    if (tid < 128) {
        float ss = 0.f;
        #pragma unroll 8
        for (int c = 0; c < C_; c++) {
            float v = __bfloat162float(xbf[c * LDX + tid]);
            ss = fmaf(v, v, ss);
        }
        float r = (s0 + tid < S_) ? (1.0f / fmaxf(sqrtf(ss), 1e-12f)) : 0.f;
        rn[tid] = r;
        g_rnorm[n * SPAD + s0 + tid] = r;
    }
    __syncthreads();

    // --- scale xbf in place by rn[s] ---
    {
        unsigned* xw = (unsigned*)xbf;
        for (int i = tid; i < 128 * 64; i += 256) {
            int c = i >> 6, sw = i & 63;
            unsigned v = xw[c * (LDX / 2) + sw];
            union { __nv_bfloat16 h[2]; unsigned u; } u;
            u.u = v;
            u.h[0] = __float2bfloat16_rn(__bfloat162float(u.h[0]) * rn[2 * sw]);
            u.h[1] = __float2bfloat16_rn(__bfloat162float(u.h[1]) * rn[2 * sw + 1]);
            xw[c * (LDX / 2) + sw] = u.u;
        }
    }
    __syncthreads();

    // --- HMMA: logits[s][k] = xn[s][c] . w[k][c] ---
    const unsigned xb_u = smem_u32(xbf), wb_u = smem_u32(wbf);
    const int msb = (wid & 3) * 32, ksb = (wid >> 2) * 32;
    float acc[2][4][4];
    #pragma unroll
    for (int i = 0; i < 2; i++)
        #pragma unroll
        for (int j = 0; j < 4; j++)
            #pragma unroll
            for (int q = 0; q < 4; q++) acc[i][j][q] = 0.f;

    const int lb = lane >> 3, lr = lane & 7, lb2 = (lane >> 3) & 1;
    #pragma unroll
    for (int kc = 0; kc < 8; kc++) {
        const int c0 = kc * 16;
        unsigned af[2][4], bfr[4][2];
        #pragma unroll
        for (int mt = 0; mt < 2; mt++) {
            unsigned addr = xb_u +
                ((unsigned)((c0 + ((lb & 2) ? 8 : 0) + lr) * LDX +
                            (msb + 16 * mt) + ((lb & 1) ? 8 : 0)) << 1);
            ldsm4t(addr, af[mt][0], af[mt][1], af[mt][2], af[mt][3]);
        }
        #pragma unroll
        for (int nt = 0; nt < 4; nt++) {
            unsigned addr = wb_u +
                ((unsigned)((ksb + 8 * nt + lr) * LDX + c0 + lb2 * 8) << 1);
            ldsm2(addr, bfr[nt][0], bfr[nt][1]);
        }
        #pragma unroll
        for (int mt = 0; mt < 2; mt++)
            #pragma unroll
            for (int nt = 0; nt < 4; nt++) mma_bf16(acc[mt][nt], af[mt], bfr[nt]);
    }
    // write logits to ls
    #pragma unroll
    for (int mt = 0; mt < 2; mt++)
        #pragma unroll
        for (int nt = 0; nt < 4; nt++) {
            int row = msb + 16 * mt + (lane >> 2);
            int col = ksb + 8 * nt + 2 * (lane & 3);
            ls[row * LDL + col]       = acc[mt][nt][0];
            ls[row * LDL + col + 1]   = acc[mt][nt][1];
            ls[(row + 8) * LDL + col]     = acc[mt][nt][2];
            ls[(row + 8) * LDL + col + 1] = acc[mt][nt][3];
        }
    __syncthreads();

    // --- softmax per pixel (FMA-pipe exp, no MUFU) ---
    if (tid < 128) {
        const int s = tid;
        const bool valid = (s0 + s) < S_;
        float m = -1e30f;
        #pragma unroll 8
        for (int k = 0; k < 64; k++) m = fmaxf(m, ls[s * LDL + k]);
        float sum = 0.f;
        #pragma unroll 8
        for (int k = 0; k < 64; k++) {
            float e = fexp(ls[s * LDL + k] - m);
            sum += e;
            ls[s * LDL + k] = e;
        }
        float rinv = valid ? (1.0f / sum) : 0.f;
        #pragma unroll 8
        for (int k = 0; k < 64; k++)
            ast[k * LDX + s] = __float2bfloat16_rn(ls[s * LDL + k] * rinv);
    }
    __syncthreads();

    // --- asum partials (sum of stored bf16 a) ---
    if (tid < 128) {
        int k = tid & 63, h = tid >> 6;
        float ssum = 0.f;
        #pragma unroll 8
        for (int u = 0; u < 64; u++) ssum += __bfloat162float(ast[k * LDX + h * 64 + u]);
        asums[tid] = ssum;
    }
    __syncthreads();
    if (tid < 64) g_asump[(n * NT + t0) * K_ + tid] = asums[tid] + asums[tid + 64];

    // --- store a[k][s] bf16 (coalesced) ---
    for (int i = tid; i < K_ * 16; i += 256) {
        int k = i >> 4, g = i & 15;
        uint4 v = *(const uint4*)(ast + k * LDX + 8 * g);
        *(uint4*)(g_abf + (size_t)(n * K_ + k) * SPAD + s0 + 8 * g) = v;
    }
}

// ============================ kF2 =============================================
// vlad partials [c][k] += xn[c][s] . a[k][s] over s-tiles (fused x read+scale)
#define F2_XBF 0
#define F2_AS  (F2_XBF + C_ * LDX * 2)   // 34816
#define F2_RN  (F2_AS + K_ * LDX * 2)    // 52224
#define F2_BYTES (F2_RN + 512)           // 52736
__global__ __launch_bounds__(256) void kF2(const float* __restrict__ x) {
    extern __shared__ char smc[];
    __nv_bfloat16* xbf = (__nv_bfloat16*)(smc + F2_XBF);  // [128 c][LDX s]
    __nv_bfloat16* as  = (__nv_bfloat16*)(smc + F2_AS);   // [64 k][LDX s]
    float* rn = (float*)(smc + F2_RN);                    // [128]

    const int tid = threadIdx.x, lane = tid & 31, wid = tid >> 5;
    const int n = blockIdx.y, p = blockIdx.x;
    const int tbeg = p * 4;
    const int tend = min(tbeg + 4, NT);

    const unsigned xb_u = smem_u32(xbf), as_u = smem_u32(as);
    const int csb = (wid & 3) * 32, ksb = (wid >> 2) * 32;
    const int lb = lane >> 3, lr = lane & 7, lb2 = (lane >> 3) & 1;

    float acc[2][4][4];
    #pragma unroll
    for (int i = 0; i < 2; i++)
        #pragma unroll
        for (int j = 0; j < 4; j++)
            #pragma unroll
            for (int q = 0; q < 4; q++) acc[i][j][q] = 0.f;

    for (int t = tbeg; t < tend; t++) {
        const int s0 = t * 128;
        __syncthreads();   // smem free from previous iteration
        if (tid < 128) rn[tid] = g_rnorm[n * SPAD + s0 + tid];
        // a tile [k][s]: full 128-wide rows (4 slices of 8 bf16 per thread)
        {
            const int k = tid >> 2, q = tid & 3;
            const __nv_bfloat16* src = g_abf + (size_t)(n * K_ + k) * SPAD + s0;
            #pragma unroll
            for (int j = 0; j < 4; j++) {
                int sl = 8 * q + 32 * j;
                *(uint4*)(as + k * LDX + sl) = *(const uint4*)(src + sl);
            }
        }
        __syncthreads();   // rn visible
        // x tile -> scaled bf16
        {
            const int c = tid >> 1, h = tid & 1;
            const float* xr = x + ((size_t)n * C_ + c) * S_;
            #pragma unroll
            for (int q = 0; q < 16; q++) {
                int sl = h * 64 + 4 * q, s = s0 + sl;
                float4 v = make_float4(0.f, 0.f, 0.f, 0.f);
                if (s + 4 <= S_) v = *(const float4*)(xr + s);
                unsigned hi, lo = pack4bf(v.x * rn[sl], v.y * rn[sl + 1],
                                          v.z * rn[sl + 2], v.w * rn[sl + 3], hi);
                *(uint2*)(xbf + c * LDX + sl) = make_uint2(lo, hi);
            }
        }
        __syncthreads();   // tiles ready

        #pragma unroll
        for (int ks = 0; ks < 8; ks++) {
            const int sst = ks * 16;
            unsigned af[2][4], bfr[4][2];
            #pragma unroll
            for (int mt = 0; mt < 2; mt++) {
                unsigned addr = xb_u +
                    ((unsigned)((csb + 16 * mt + (lb & 1) * 8 + lr) * LDX +
                                sst + ((lb & 2) ? 8 : 0)) << 1);
                ldsm4(addr, af[mt][0], af[mt][1], af[mt][2], af[mt][3]);
            }
            #pragma unroll
            for (int nt = 0; nt < 4; nt++) {
                unsigned addr = as_u +
                    ((unsigned)((ksb + 8 * nt + lr) * LDX + sst + lb2 * 8) << 1);
                ldsm2(addr, bfr[nt][0], bfr[nt][1]);
            }
            #pragma unroll
            for (int mt = 0; mt < 2; mt++)
                #pragma unroll
                for (int nt = 0; nt < 4; nt++) mma_bf16(acc[mt][nt], af[mt], bfr[nt]);
        }
    }

    // write partials [c][k]
    float* dst = g_d2part + (size_t)(n * SPLIT + p) * C_ * K_;
    #pragma unroll
    for (int mt = 0; mt < 2; mt++)
        #pragma unroll
        for (int nt = 0; nt < 4; nt++) {
            int row = csb + 16 * mt + (lane >> 2);
            int col = ksb + 8 * nt + 2 * (lane & 3);
            *(float2*)(dst + row * K_ + col) = make_float2(acc[mt][nt][0], acc[mt][nt][1]);
            *(float2*)(dst + (row + 8) * K_ + col) = make_float2(acc[mt][nt][2], acc[mt][nt][3]);
        }
}

// ============================ kC1 / kC2 ======================================
__global__ __launch_bounds__(128) void kC1(const float* __restrict__ cent,
                                           float* __restrict__ out) {
    const int n = blockIdx.y, k = blockIdx.x, c = threadIdx.x;
    float asum = 0.f;
    #pragma unroll 1
    for (int t = 0; t < NT; t++) asum += g_asump[(n * NT + t) * K_ + k];
    float v = 0.f;
    #pragma unroll
    for (int p = 0; p < SPLIT; p++)
        v += g_d2part[(size_t)(n * SPLIT + p) * C_ * K_ + c * K_ + k];
    v -= asum * cent[k * C_ + c];

    float ss = v * v;
    #pragma unroll
    for (int o = 16; o; o >>= 1) ss += __shfl_xor_sync(0xffffffffu, ss, o);
    __shared__ float sred[4];
    if ((c & 31) == 0) sred[c >> 5] = ss;
    __syncthreads();
    float tot = sred[0] + sred[1] + sred[2] + sred[3];
    float d = fmaxf(sqrtf(tot), 1e-12f);
    out[((size_t)n * K_ + k) * C_ + c] = v / d;
    if (c == 0) g_rowss[n * K_ + k] = tot / (d * d);
}

__global__ __launch_bounds__(256) void kC2(float* __restrict__ out) {
    const int n = blockIdx.x, tid = threadIdx.x;
    __shared__ float sred[2];
    if (tid < 64) {
        float ss = g_rowss[n * 64 + tid];
        #pragma unroll
        for (int o = 16; o; o >>= 1) ss += __shfl_xor_sync(0xffffffffu, ss, o);
        if ((tid & 31) == 0) sred[tid >> 5] = ss;
    }
    __syncthreads();
    float d = fmaxf(sqrtf(sred[0] + sred[1]), 1e-12f);
    float r = 1.0f / d;
    float* o = out + (size_t)n * K_ * C_;
    for (int i = tid; i < K_ * C_; i += 256) o[i] *= r;
}

// ============================ launch =========================================
extern "C" void kernel_launch(void* const* d_in, const int* in_sizes, int n_in,
                              void* d_out, int out_size) {
    const float* x    = (const float*)d_in[0];
    const float* w    = (const float*)d_in[1];
    const float* cent = (const float*)d_in[2];
    float* out = (float*)d_out;

    cudaFuncSetAttribute(kF1, cudaFuncAttributeMaxDynamicSharedMemorySize, F1_BYTES);
    cudaFuncSetAttribute(kF2, cudaFuncAttributeMaxDynamicSharedMemorySize, F2_BYTES);

    kF1<<<dim3(NT, N_), 256, F1_BYTES>>>(x, w);
    kF2<<<dim3(SPLIT, N_), 256, F2_BYTES>>>(x);
    kC1<<<dim3(K_, N_), 128>>>(cent, out);
    kC2<<<N_, 256>>>(out);
}

// round 10
// speedup vs baseline: 2.7719x; 1.3072x over previous
#include <cuda_runtime.h>
#include <cuda_bf16.h>

#define N_ 64
#define C_ 128
#define S_ 3600
#define K_ 64
#define NT 29              // tiles of 128 pixels
#define SPLIT 15           // 14 CTArows of 2 tiles + 1 of 1 tile
#define LDX 136            // bf16 row stride (272B)

// ---------------- static device scratch --------------------------------------
__device__ float g_d2part[(size_t)N_ * SPLIT * K_ * C_];   // [n][p][k][c]
__device__ float g_asump[N_ * SPLIT * K_];

// ---------------- helpers -----------------------------------------------------
__device__ __forceinline__ unsigned smem_u32(const void* p) {
    unsigned a;
    asm("{ .reg .u64 t; cvta.to.shared.u64 t, %1; cvt.u32.u64 %0, t; }"
        : "=r"(a) : "l"(p));
    return a;
}
__device__ __forceinline__ void ldsm4t(unsigned addr, unsigned& r0, unsigned& r1,
                                       unsigned& r2, unsigned& r3) {
    asm volatile("ldmatrix.sync.aligned.m8n8.x4.trans.shared.b16 {%0,%1,%2,%3}, [%4];"
                 : "=r"(r0), "=r"(r1), "=r"(r2), "=r"(r3) : "r"(addr));
}
__device__ __forceinline__ void ldsm4(unsigned addr, unsigned& r0, unsigned& r1,
                                      unsigned& r2, unsigned& r3) {
    asm volatile("ldmatrix.sync.aligned.m8n8.x4.shared.b16 {%0,%1,%2,%3}, [%4];"
                 : "=r"(r0), "=r"(r1), "=r"(r2), "=r"(r3) : "r"(addr));
}
__device__ __forceinline__ void ldsm2(unsigned addr, unsigned& r0, unsigned& r1) {
    asm volatile("ldmatrix.sync.aligned.m8n8.x2.shared.b16 {%0,%1}, [%2];"
                 : "=r"(r0), "=r"(r1) : "r"(addr));
}
__device__ __forceinline__ void mma_bf16(float* d, const unsigned* a, const unsigned* b) {
    asm volatile("mma.sync.aligned.m16n8k16.row.col.f32.bf16.bf16.f32 "
                 "{%0,%1,%2,%3}, {%4,%5,%6,%7}, {%8,%9}, {%0,%1,%2,%3};"
                 : "+f"(d[0]), "+f"(d[1]), "+f"(d[2]), "+f"(d[3])
                 : "r"(a[0]), "r"(a[1]), "r"(a[2]), "r"(a[3]), "r"(b[0]), "r"(b[1]));
}
__device__ __forceinline__ unsigned pack4bf(float a, float b, float c, float d,
                                            unsigned& hi) {
    union { __nv_bfloat16 h[2]; unsigned u; } lo_u, hi_u;
    lo_u.h[0] = __float2bfloat16_rn(a); lo_u.h[1] = __float2bfloat16_rn(b);
    hi_u.h[0] = __float2bfloat16_rn(c); hi_u.h[1] = __float2bfloat16_rn(d);
    hi = hi_u.u;
    return lo_u.u;
}
// exp(x) on the FMA/ALU pipes (no MUFU). x <= 0 expected; rel err ~2e-6.
__device__ __forceinline__ float fexp(float x) {
    x = fmaxf(x, -60.0f);
    float t = fmaf(x, 1.44269504089f, 12582912.0f);   // 2^23*1.5 magic round
    int ei = __float_as_int(t) - 0x4B400000;          // integer part (signed)
    float i = t - 12582912.0f;
    float f = fmaf(x, 1.44269504089f, -i);            // frac in [-0.5,0.5]
    float p = 1.33335581e-3f;
    p = fmaf(p, f, 9.61812910e-3f);
    p = fmaf(p, f, 5.55041087e-2f);
    p = fmaf(p, f, 2.40226507e-1f);
    p = fmaf(p, f, 6.93147181e-1f);
    p = fmaf(p, f, 1.0f);                             // 2^f
    return __int_as_float(__float_as_int(p) + (ei << 23));
}

// ============================ kFA (fully fused) ===============================
// per 128-px tile: x->bf16, rnorm, logits HMMA, softmax (a' = a*rn), VLAD HMMA
#define XBF_OFF 0
#define WBF_OFF 34816
#define AST_OFF 52224
#define RN_OFF  69632
#define NRM_OFF 70144
#define ASR_OFF 70656
#define FA_BYTES 71680
__global__ void __launch_bounds__(256, 2) kFA(const float* __restrict__ x,
                                              const float* __restrict__ w) {
    extern __shared__ char smc[];
    __nv_bfloat16* xbf = (__nv_bfloat16*)(smc + XBF_OFF);  // [128 c][LDX s] raw x
    __nv_bfloat16* wbf = (__nv_bfloat16*)(smc + WBF_OFF);  // [64 k][LDX c]
    __nv_bfloat16* ast = (__nv_bfloat16*)(smc + AST_OFF);  // [64 k][LDX s] logits->a'
    float* rn  = (float*)(smc + RN_OFF);                   // 1/max(||x||,eps) (0 if pad)
    float* nrm = (float*)(smc + NRM_OFF);                  // max(||x||,eps)   (0 if pad)
    float* asr = (float*)(smc + ASR_OFF);                  // asum reduce [256]

    const int tid = threadIdx.x, lane = tid & 31, wid = tid >> 5;
    const int n = blockIdx.y, p = blockIdx.x;
    const int tbeg = 2 * p, tend = min(2 * p + 2, NT);

    const unsigned xb_u = smem_u32(xbf), wb_u = smem_u32(wbf), as_u = smem_u32(ast);
    const int msb = (wid & 3) * 32;    // s-block (HMMA1) / c-block (VLAD)
    const int ksb = (wid >> 2) * 32;   // k-block
    const int lb = lane >> 3, lr = lane & 7, lb2 = (lane >> 3) & 1;

    // --- load w once: [k][c] fp32 -> bf16 ---
    {
        const int k = tid >> 2, qq = tid & 3;
        const float* wr = w + k * C_;
        #pragma unroll
        for (int j = 0; j < 8; j++) {
            int c = qq * 32 + 4 * j;
            float4 v = *(const float4*)(wr + c);
            unsigned hi, lo = pack4bf(v.x, v.y, v.z, v.w, hi);
            *(uint2*)(wbf + k * LDX + c) = make_uint2(lo, hi);
        }
    }

    float acc2[2][4][4];          // VLAD accumulators [c][k], persist across tiles
    #pragma unroll
    for (int i = 0; i < 2; i++)
        #pragma unroll
        for (int j = 0; j < 4; j++)
            #pragma unroll
            for (int q = 0; q < 4; q++) acc2[i][j][q] = 0.f;
    float asumr = 0.f;
    const int kA = tid & 63, qA = tid >> 6;

    for (int t = tbeg; t < tend; t++) {
        const int s0 = t * 128;
        __syncthreads();   // prior tile reads done (and wbf visible on iter 0)

        // --- load x tile raw fp32 -> bf16 [c][s] ---
        {
            const int c = tid >> 1, h = tid & 1;
            const float* xr = x + ((size_t)n * C_ + c) * S_;
            #pragma unroll
            for (int q = 0; q < 16; q++) {
                int s = s0 + h * 64 + 4 * q;
                float4 v = make_float4(0.f, 0.f, 0.f, 0.f);
                if (s + 4 <= S_) v = *(const float4*)(xr + s);
                unsigned hi, lo = pack4bf(v.x, v.y, v.z, v.w, hi);
                *(uint2*)(xbf + c * LDX + h * 64 + 4 * q) = make_uint2(lo, hi);
            }
        }
        __syncthreads();

        // --- rnorm (2 threads/pixel, staggered banks) ---
        {
            const int s = tid >> 1, h = tid & 1;
            float ss = 0.f;
            #pragma unroll 8
            for (int cc = 0; cc < 64; cc++) {
                int c = 64 * h + ((cc + 4 * h) & 63);
                float v = __bfloat162float(xbf[c * LDX + s]);
                ss = fmaf(v, v, ss);
            }
            ss += __shfl_xor_sync(0xffffffffu, ss, 1);
            if (h == 0) {
                bool valid = (s0 + s) < S_;
                float nm = fmaxf(sqrtf(ss), 1e-12f);
                rn[s]  = valid ? (1.0f / nm) : 0.f;
                nrm[s] = valid ? nm : 0.f;
            }
        }

        // --- HMMA1: l0[s][k] = x[s][c] . w[k][c]; store bf16 -> ast[k][s] ---
        {
            float la[2][4][4];
            #pragma unroll
            for (int i = 0; i < 2; i++)
                #pragma unroll
                for (int j = 0; j < 4; j++)
                    #pragma unroll
                    for (int q = 0; q < 4; q++) la[i][j][q] = 0.f;
            #pragma unroll
            for (int kc = 0; kc < 8; kc++) {
                const int c0 = kc * 16;
                unsigned af[2][4], bfr[4][2];
                #pragma unroll
                for (int mt = 0; mt < 2; mt++) {
                    unsigned addr = xb_u +
                        ((unsigned)((c0 + ((lb & 2) ? 8 : 0) + lr) * LDX +
                                    (msb + 16 * mt) + ((lb & 1) ? 8 : 0)) << 1);
                    ldsm4t(addr, af[mt][0], af[mt][1], af[mt][2], af[mt][3]);
                }
                #pragma unroll
                for (int nt = 0; nt < 4; nt++) {
                    unsigned addr = wb_u +
                        ((unsigned)((ksb + 8 * nt + lr) * LDX + c0 + lb2 * 8) << 1);
                    ldsm2(addr, bfr[nt][0], bfr[nt][1]);
                }
                #pragma unroll
                for (int mt = 0; mt < 2; mt++)
                    #pragma unroll
                    for (int nt = 0; nt < 4; nt++) mma_bf16(la[mt][nt], af[mt], bfr[nt]);
            }
            #pragma unroll
            for (int mt = 0; mt < 2; mt++)
                #pragma unroll
                for (int nt = 0; nt < 4; nt++) {
                    int row = msb + 16 * mt + (lane >> 2);
                    int col = ksb + 8 * nt + 2 * (lane & 3);
                    ast[col * LDX + row]           = __float2bfloat16_rn(la[mt][nt][0]);
                    ast[(col + 1) * LDX + row]     = __float2bfloat16_rn(la[mt][nt][1]);
                    ast[col * LDX + row + 8]       = __float2bfloat16_rn(la[mt][nt][2]);
                    ast[(col + 1) * LDX + row + 8] = __float2bfloat16_rn(la[mt][nt][3]);
                }
        }
        __syncthreads();

        // --- softmax per pixel; write a' = a * rn[s] back into ast ---
        {
            const int s = tid >> 1, h = tid & 1;
            const float r = rn[s];
            float lv[32];
            #pragma unroll
            for (int j = 0; j < 32; j++) {
                int k = 32 * h + ((j + 4 * h) & 31);
                lv[j] = __bfloat162float(ast[k * LDX + s]) * r;
            }
            float m = lv[0];
            #pragma unroll
            for (int j = 1; j < 32; j++) m = fmaxf(m, lv[j]);
            m = fmaxf(m, __shfl_xor_sync(0xffffffffu, m, 1));
            float sum = 0.f;
            #pragma unroll
            for (int j = 0; j < 32; j++) {
                lv[j] = fexp(lv[j] - m);
                sum += lv[j];
            }
            sum += __shfl_xor_sync(0xffffffffu, sum, 1);
            float sc = r / sum;      // folds rn into a; 0 for padded pixels
            #pragma unroll
            for (int j = 0; j < 32; j++) {
                int k = 32 * h + ((j + 4 * h) & 31);
                ast[k * LDX + s] = __float2bfloat16_rn(lv[j] * sc);
            }
        }
        __syncthreads();

        // --- asum accumulate: asum[k] += sum_s a'[k][s] * nrm[s] ---
        #pragma unroll 8
        for (int u = 0; u < 32; u++) {
            int s = qA * 32 + u;
            asumr = fmaf(__bfloat162float(ast[kA * LDX + s]), nrm[s], asumr);
        }

        // --- VLAD HMMA: acc2[c][k] += x_raw[c][s] . a'[k][s] ---
        #pragma unroll
        for (int ks = 0; ks < 8; ks++) {
            const int sst = ks * 16;
            unsigned af[2][4], bfr[4][2];
            #pragma unroll
            for (int mt = 0; mt < 2; mt++) {
                unsigned addr = xb_u +
                    ((unsigned)((msb + 16 * mt + (lb & 1) * 8 + lr) * LDX +
                                sst + ((lb & 2) ? 8 : 0)) << 1);
                ldsm4(addr, af[mt][0], af[mt][1], af[mt][2], af[mt][3]);
            }
            #pragma unroll
            for (int nt = 0; nt < 4; nt++) {
                unsigned addr = as_u +
                    ((unsigned)((ksb + 8 * nt + lr) * LDX + sst + lb2 * 8) << 1);
                ldsm2(addr, bfr[nt][0], bfr[nt][1]);
            }
            #pragma unroll
            for (int mt = 0; mt < 2; mt++)
                #pragma unroll
                for (int nt = 0; nt < 4; nt++) mma_bf16(acc2[mt][nt], af[mt], bfr[nt]);
        }
    }

    // --- asum partials out ---
    asr[tid] = asumr;
    __syncthreads();           // also: all VLAD reads of xbf done -> safe to reuse
    if (tid < 64)
        g_asump[(n * SPLIT + p) * K_ + tid] =
            asr[tid] + asr[tid + 64] + asr[tid + 128] + asr[tid + 192];

    // --- transpose acc2 to [k][c] via smem (reuse xbf region), store coalesced ---
    float* vo = (float*)(smc + XBF_OFF);   // [64 k][132]
    #pragma unroll
    for (int mt = 0; mt < 2; mt++)
        #pragma unroll
        for (int nt = 0; nt < 4; nt++) {
            int c_r = msb + 16 * mt + (lane >> 2);
            int k_c = ksb + 8 * nt + 2 * (lane & 3);
            vo[k_c * 132 + c_r]           = acc2[mt][nt][0];
            vo[(k_c + 1) * 132 + c_r]     = acc2[mt][nt][1];
            vo[k_c * 132 + c_r + 8]       = acc2[mt][nt][2];
            vo[(k_c + 1) * 132 + c_r + 8] = acc2[mt][nt][3];
        }
    __syncthreads();
    float* dst = g_d2part + (size_t)(n * SPLIT + p) * K_ * C_;
    for (int i = tid; i < K_ * 32; i += 256) {
        int k = i >> 5, g = i & 31;
        *(float4*)(dst + k * C_ + 4 * g) = *(const float4*)(vo + k * 132 + 4 * g);
    }
}

// ============================ kC (fused epilogue) =============================
// reduce partials, centroid subtract, row norm, global norm, store
__global__ void __launch_bounds__(256) kC(const float* __restrict__ cent,
                                          float* __restrict__ out) {
    __shared__ float vout[K_ * C_];    // 32 KB
    __shared__ float rowss_s[K_];
    __shared__ float gsc;
    const int n = blockIdx.x, tid = threadIdx.x, lane = tid & 31, wid = tid >> 5;

    // each warp: 8 rows; lane: 4 channels
    for (int r = 0; r < 8; r++) {
        const int k = wid * 8 + r;
        float asum = 0.f;
        #pragma unroll 1
        for (int p = 0; p < SPLIT; p++)
            asum += g_asump[(n * SPLIT + p) * K_ + k];
        float4 v = make_float4(0.f, 0.f, 0.f, 0.f);
        #pragma unroll 1
        for (int p = 0; p < SPLIT; p++) {
            float4 d = *(const float4*)(g_d2part +
                (size_t)(n * SPLIT + p) * K_ * C_ + k * C_ + 4 * lane);
            v.x += d.x; v.y += d.y; v.z += d.z; v.w += d.w;
        }
        float4 ce = *(const float4*)(cent + k * C_ + 4 * lane);
        v.x -= asum * ce.x; v.y -= asum * ce.y;
        v.z -= asum * ce.z; v.w -= asum * ce.w;

        float ss = v.x * v.x + v.y * v.y + v.z * v.z + v.w * v.w;
        #pragma unroll
        for (int o = 16; o; o >>= 1) ss += __shfl_xor_sync(0xffffffffu, ss, o);
        float d = fmaxf(sqrtf(ss), 1e-12f);
        float inv = 1.0f / d;
        float4 o4 = make_float4(v.x * inv, v.y * inv, v.z * inv, v.w * inv);
        *(float4*)(vout + k * C_ + 4 * lane) = o4;
        if (lane == 0) rowss_s[k] = ss / (d * d);
    }
    __syncthreads();
    if (tid < 32) {
        float s = rowss_s[tid] + rowss_s[tid + 32];
        #pragma unroll
        for (int o = 16; o; o >>= 1) s += __shfl_xor_sync(0xffffffffu, s, o);
        if (tid == 0) gsc = 1.0f / fmaxf(sqrtf(s), 1e-12f);
    }
    __syncthreads();
    const float g = gsc;
    float4* o4 = (float4*)(out + (size_t)n * K_ * C_);
    const float4* v4 = (const float4*)vout;
    for (int i = tid; i < K_ * C_ / 4; i += 256) {
        float4 v = v4[i];
        o4[i] = make_float4(v.x * g, v.y * g, v.z * g, v.w * g);
    }
}

// ============================ launch =========================================
extern "C" void kernel_launch(void* const* d_in, const int* in_sizes, int n_in,
                              void* d_out, int out_size) {
    const float* x    = (const float*)d_in[0];
    const float* w    = (const float*)d_in[1];
    const float* cent = (const float*)d_in[2];
    float* out = (float*)d_out;

    cudaFuncSetAttribute(kFA, cudaFuncAttributeMaxDynamicSharedMemorySize, FA_BYTES);

    kFA<<<dim3(SPLIT, N_), 256, FA_BYTES>>>(x, w);
    kC<<<N_, 256>>>(cent, out);
}

// round 12
// speedup vs baseline: 4.9237x; 1.7763x over previous
#include <cuda_runtime.h>
#include <cuda_bf16.h>

#define N_ 64
#define C_ 128
#define S_ 3600
#define K_ 64
#define NT 29              // tiles of 128 pixels
#define SPLIT 15           // 14 CTArows of 2 tiles + 1 of 1 tile
#define LDX 136            // bf16 row stride (272B)

// ---------------- static device scratch --------------------------------------
__device__ float g_d2part[(size_t)N_ * SPLIT * K_ * C_];   // [n][p][k][c]
__device__ float g_asump[N_ * SPLIT * K_];
__device__ float g_rowss[N_ * K_];

// ---------------- helpers -----------------------------------------------------
__device__ __forceinline__ unsigned smem_u32(const void* p) {
    unsigned a;
    asm("{ .reg .u64 t; cvta.to.shared.u64 t, %1; cvt.u32.u64 %0, t; }"
        : "=r"(a) : "l"(p));
    return a;
}
__device__ __forceinline__ void ldsm4t(unsigned addr, unsigned& r0, unsigned& r1,
                                       unsigned& r2, unsigned& r3) {
    asm volatile("ldmatrix.sync.aligned.m8n8.x4.trans.shared.b16 {%0,%1,%2,%3}, [%4];"
                 : "=r"(r0), "=r"(r1), "=r"(r2), "=r"(r3) : "r"(addr));
}
__device__ __forceinline__ void ldsm4(unsigned addr, unsigned& r0, unsigned& r1,
                                      unsigned& r2, unsigned& r3) {
    asm volatile("ldmatrix.sync.aligned.m8n8.x4.shared.b16 {%0,%1,%2,%3}, [%4];"
                 : "=r"(r0), "=r"(r1), "=r"(r2), "=r"(r3) : "r"(addr));
}
__device__ __forceinline__ void ldsm2(unsigned addr, unsigned& r0, unsigned& r1) {
    asm volatile("ldmatrix.sync.aligned.m8n8.x2.shared.b16 {%0,%1}, [%2];"
                 : "=r"(r0), "=r"(r1) : "r"(addr));
}
__device__ __forceinline__ void mma_bf16(float* d, const unsigned* a, const unsigned* b) {
    asm volatile("mma.sync.aligned.m16n8k16.row.col.f32.bf16.bf16.f32 "
                 "{%0,%1,%2,%3}, {%4,%5,%6,%7}, {%8,%9}, {%0,%1,%2,%3};"
                 : "+f"(d[0]), "+f"(d[1]), "+f"(d[2]), "+f"(d[3])
                 : "r"(a[0]), "r"(a[1]), "r"(a[2]), "r"(a[3]), "r"(b[0]), "r"(b[1]));
}
__device__ __forceinline__ unsigned pack4bf(float a, float b, float c, float d,
                                            unsigned& hi) {
    union { __nv_bfloat16 h[2]; unsigned u; } lo_u, hi_u;
    lo_u.h[0] = __float2bfloat16_rn(a); lo_u.h[1] = __float2bfloat16_rn(b);
    hi_u.h[0] = __float2bfloat16_rn(c); hi_u.h[1] = __float2bfloat16_rn(d);
    hi = hi_u.u;
    return lo_u.u;
}
// exp(x) on the FMA/ALU pipes (no MUFU). x <= 0 expected; rel err ~2e-6.
__device__ __forceinline__ float fexp(float x) {
    x = fmaxf(x, -60.0f);
    float t = fmaf(x, 1.44269504089f, 12582912.0f);   // 2^23*1.5 magic round
    int ei = __float_as_int(t) - 0x4B400000;          // integer part (signed)
    float i = t - 12582912.0f;
    float f = fmaf(x, 1.44269504089f, -i);            // frac in [-0.5,0.5]
    float p = 1.33335581e-3f;
    p = fmaf(p, f, 9.61812910e-3f);
    p = fmaf(p, f, 5.55041087e-2f);
    p = fmaf(p, f, 2.40226507e-1f);
    p = fmaf(p, f, 6.93147181e-1f);
    p = fmaf(p, f, 1.0f);                             // 2^f
    return __int_as_float(__float_as_int(p) + (ei << 23));
}

// ============================ kFA (fully fused) ===============================
// per 128-px tile: x->bf16, rnorm, logits HMMA, softmax (a' = a*rn), VLAD HMMA
#define XBF_OFF 0
#define WBF_OFF 34816
#define AST_OFF 52224
#define RN_OFF  69632
#define NRM_OFF 70144
#define ASR_OFF 70656
#define FA_BYTES 71680
__global__ void __launch_bounds__(256, 2) kFA(const float* __restrict__ x,
                                              const float* __restrict__ w) {
    extern __shared__ char smc[];
    __nv_bfloat16* xbf = (__nv_bfloat16*)(smc + XBF_OFF);  // [128 c][LDX s] raw x
    __nv_bfloat16* wbf = (__nv_bfloat16*)(smc + WBF_OFF);  // [64 k][LDX c]
    __nv_bfloat16* ast = (__nv_bfloat16*)(smc + AST_OFF);  // [64 k][LDX s] logits->a'
    float* rn  = (float*)(smc + RN_OFF);                   // 1/max(||x||,eps) (0 if pad)
    float* nrm = (float*)(smc + NRM_OFF);                  // max(||x||,eps)   (0 if pad)
    float* asr = (float*)(smc + ASR_OFF);                  // asum reduce [256]

    const int tid = threadIdx.x, lane = tid & 31, wid = tid >> 5;
    const int n = blockIdx.y, p = blockIdx.x;
    const int tbeg = 2 * p, tend = min(2 * p + 2, NT);

    const unsigned xb_u = smem_u32(xbf), wb_u = smem_u32(wbf), as_u = smem_u32(ast);
    const int msb = (wid & 3) * 32;    // s-block (HMMA1) / c-block (VLAD)
    const int ksb = (wid >> 2) * 32;   // k-block
    const int lb = lane >> 3, lr = lane & 7, lb2 = (lane >> 3) & 1;

    // --- load w once: [k][c] fp32 -> bf16 ---
    {
        const int k = tid >> 2, qq = tid & 3;
        const float* wr = w + k * C_;
        #pragma unroll
        for (int j = 0; j < 8; j++) {
            int c = qq * 32 + 4 * j;
            float4 v = *(const float4*)(wr + c);
            unsigned hi, lo = pack4bf(v.x, v.y, v.z, v.w, hi);
            *(uint2*)(wbf + k * LDX + c) = make_uint2(lo, hi);
        }
    }

    float acc2[2][4][4];          // VLAD accumulators [c][k], persist across tiles
    #pragma unroll
    for (int i = 0; i < 2; i++)
        #pragma unroll
        for (int j = 0; j < 4; j++)
            #pragma unroll
            for (int q = 0; q < 4; q++) acc2[i][j][q] = 0.f;
    float asumr = 0.f;
    const int kA = tid & 63, qA = tid >> 6;

    for (int t = tbeg; t < tend; t++) {
        const int s0 = t * 128;
        __syncthreads();   // prior tile reads done (and wbf visible on iter 0)

        // --- load x tile raw fp32 -> bf16 [c][s] ---
        {
            const int c = tid >> 1, h = tid & 1;
            const float* xr = x + ((size_t)n * C_ + c) * S_;
            #pragma unroll
            for (int q = 0; q < 16; q++) {
                int s = s0 + h * 64 + 4 * q;
                float4 v = make_float4(0.f, 0.f, 0.f, 0.f);
                if (s + 4 <= S_) v = *(const float4*)(xr + s);
                unsigned hi, lo = pack4bf(v.x, v.y, v.z, v.w, hi);
                *(uint2*)(xbf + c * LDX + h * 64 + 4 * q) = make_uint2(lo, hi);
            }
        }
        __syncthreads();

        // --- rnorm (2 threads/pixel, staggered banks) ---
        {
            const int s = tid >> 1, h = tid & 1;
            float ss = 0.f;
            #pragma unroll 8
            for (int cc = 0; cc < 64; cc++) {
                int c = 64 * h + ((cc + 4 * h) & 63);
                float v = __bfloat162float(xbf[c * LDX + s]);
                ss = fmaf(v, v, ss);
            }
            ss += __shfl_xor_sync(0xffffffffu, ss, 1);
            if (h == 0) {
                bool valid = (s0 + s) < S_;
                float nm = fmaxf(sqrtf(ss), 1e-12f);
                rn[s]  = valid ? (1.0f / nm) : 0.f;
                nrm[s] = valid ? nm : 0.f;
            }
        }

        // --- HMMA1: l0[s][k] = x[s][c] . w[k][c]; store bf16 -> ast[k][s] ---
        {
            float la[2][4][4];
            #pragma unroll
            for (int i = 0; i < 2; i++)
                #pragma unroll
                for (int j = 0; j < 4; j++)
                    #pragma unroll
                    for (int q = 0; q < 4; q++) la[i][j][q] = 0.f;
            #pragma unroll
            for (int kc = 0; kc < 8; kc++) {
                const int c0 = kc * 16;
                unsigned af[2][4], bfr[4][2];
                #pragma unroll
                for (int mt = 0; mt < 2; mt++) {
                    unsigned addr = xb_u +
                        ((unsigned)((c0 + ((lb & 2) ? 8 : 0) + lr) * LDX +
                                    (msb + 16 * mt) + ((lb & 1) ? 8 : 0)) << 1);
                    ldsm4t(addr, af[mt][0], af[mt][1], af[mt][2], af[mt][3]);
                }
                #pragma unroll
                for (int nt = 0; nt < 4; nt++) {
                    unsigned addr = wb_u +
                        ((unsigned)((ksb + 8 * nt + lr) * LDX + c0 + lb2 * 8) << 1);
                    ldsm2(addr, bfr[nt][0], bfr[nt][1]);
                }
                #pragma unroll
                for (int mt = 0; mt < 2; mt++)
                    #pragma unroll
                    for (int nt = 0; nt < 4; nt++) mma_bf16(la[mt][nt], af[mt], bfr[nt]);
            }
            #pragma unroll
            for (int mt = 0; mt < 2; mt++)
                #pragma unroll
                for (int nt = 0; nt < 4; nt++) {
                    int row = msb + 16 * mt + (lane >> 2);
                    int col = ksb + 8 * nt + 2 * (lane & 3);
                    ast[col * LDX + row]           = __float2bfloat16_rn(la[mt][nt][0]);
                    ast[(col + 1) * LDX + row]     = __float2bfloat16_rn(la[mt][nt][1]);
                    ast[col * LDX + row + 8]       = __float2bfloat16_rn(la[mt][nt][2]);
                    ast[(col + 1) * LDX + row + 8] = __float2bfloat16_rn(la[mt][nt][3]);
                }
        }
        __syncthreads();

        // --- softmax per pixel; write a' = a * rn[s] back into ast ---
        {
            const int s = tid >> 1, h = tid & 1;
            const float r = rn[s];
            float lv[32];
            #pragma unroll
            for (int j = 0; j < 32; j++) {
                int k = 32 * h + ((j + 4 * h) & 31);
                lv[j] = __bfloat162float(ast[k * LDX + s]) * r;
            }
            float m = lv[0];
            #pragma unroll
            for (int j = 1; j < 32; j++) m = fmaxf(m, lv[j]);
            m = fmaxf(m, __shfl_xor_sync(0xffffffffu, m, 1));
            float sum = 0.f;
            #pragma unroll
            for (int j = 0; j < 32; j++) {
                lv[j] = fexp(lv[j] - m);
                sum += lv[j];
            }
            sum += __shfl_xor_sync(0xffffffffu, sum, 1);
            float sc = r / sum;      // folds rn into a; 0 for padded pixels
            #pragma unroll
            for (int j = 0; j < 32; j++) {
                int k = 32 * h + ((j + 4 * h) & 31);
                ast[k * LDX + s] = __float2bfloat16_rn(lv[j] * sc);
            }
        }
        __syncthreads();

        // --- asum accumulate: asum[k] += sum_s a'[k][s] * nrm[s] ---
        #pragma unroll 8
        for (int u = 0; u < 32; u++) {
            int s = qA * 32 + u;
            asumr = fmaf(__bfloat162float(ast[kA * LDX + s]), nrm[s], asumr);
        }

        // --- VLAD HMMA: acc2[c][k] += x_raw[c][s] . a'[k][s] ---
        #pragma unroll
        for (int ks = 0; ks < 8; ks++) {
            const int sst = ks * 16;
            unsigned af[2][4], bfr[4][2];
            #pragma unroll
            for (int mt = 0; mt < 2; mt++) {
                unsigned addr = xb_u +
                    ((unsigned)((msb + 16 * mt + (lb & 1) * 8 + lr) * LDX +
                                sst + ((lb & 2) ? 8 : 0)) << 1);
                ldsm4(addr, af[mt][0], af[mt][1], af[mt][2], af[mt][3]);
            }
            #pragma unroll
            for (int nt = 0; nt < 4; nt++) {
                unsigned addr = as_u +
                    ((unsigned)((ksb + 8 * nt + lr) * LDX + sst + lb2 * 8) << 1);
                ldsm2(addr, bfr[nt][0], bfr[nt][1]);
            }
            #pragma unroll
            for (int mt = 0; mt < 2; mt++)
                #pragma unroll
                for (int nt = 0; nt < 4; nt++) mma_bf16(acc2[mt][nt], af[mt], bfr[nt]);
        }
    }

    // --- asum partials out ---
    asr[tid] = asumr;
    __syncthreads();           // also: all VLAD reads of xbf done -> safe to reuse
    if (tid < 64)
        g_asump[(n * SPLIT + p) * K_ + tid] =
            asr[tid] + asr[tid + 64] + asr[tid + 128] + asr[tid + 192];

    // --- transpose acc2 to [k][c] via smem (reuse xbf region), store coalesced ---
    float* vo = (float*)(smc + XBF_OFF);   // [64 k][132]
    #pragma unroll
    for (int mt = 0; mt < 2; mt++)
        #pragma unroll
        for (int nt = 0; nt < 4; nt++) {
            int c_r = msb + 16 * mt + (lane >> 2);
            int k_c = ksb + 8 * nt + 2 * (lane & 3);
            vo[k_c * 132 + c_r]           = acc2[mt][nt][0];
            vo[(k_c + 1) * 132 + c_r]     = acc2[mt][nt][1];
            vo[k_c * 132 + c_r + 8]       = acc2[mt][nt][2];
            vo[(k_c + 1) * 132 + c_r + 8] = acc2[mt][nt][3];
        }
    __syncthreads();
    float* dst = g_d2part + (size_t)(n * SPLIT + p) * K_ * C_;
    for (int i = tid; i < K_ * 32; i += 256) {
        int k = i >> 5, g = i & 31;
        *(float4*)(dst + k * C_ + 4 * g) = *(const float4*)(vo + k * 132 + 4 * g);
    }
}

// ============================ kC1 =============================================
// per (n,k): reduce 15 partials (MLP=15, coalesced), centroid subtract,
// row normalize, store row + row sumsq
__global__ __launch_bounds__(128) void kC1(const float* __restrict__ cent,
                                           float* __restrict__ out) {
    const int n = blockIdx.y, k = blockIdx.x, c = threadIdx.x;

    float asum = 0.f;
    #pragma unroll
    for (int p = 0; p < SPLIT; p++)
        asum += g_asump[(n * SPLIT + p) * K_ + k];

    float v = 0.f;
    #pragma unroll
    for (int p = 0; p < SPLIT; p++)
        v += g_d2part[(size_t)(n * SPLIT + p) * K_ * C_ + k * C_ + c];
    v -= asum * cent[k * C_ + c];

    float ss = v * v;
    #pragma unroll
    for (int o = 16; o; o >>= 1) ss += __shfl_xor_sync(0xffffffffu, ss, o);
    __shared__ float sred[4];
    if ((c & 31) == 0) sred[c >> 5] = ss;
    __syncthreads();
    float tot = sred[0] + sred[1] + sred[2] + sred[3];
    float d = fmaxf(sqrtf(tot), 1e-12f);
    out[((size_t)n * K_ + k) * C_ + c] = v / d;
    if (c == 0) g_rowss[n * K_ + k] = tot / (d * d);
}

// ============================ kC2 =============================================
__global__ __launch_bounds__(256) void kC2(float* __restrict__ out) {
    const int n = blockIdx.x, tid = threadIdx.x;
    __shared__ float sred[2];
    if (tid < 64) {
        float ss = g_rowss[n * 64 + tid];
        #pragma unroll
        for (int o = 16; o; o >>= 1) ss += __shfl_xor_sync(0xffffffffu, ss, o);
        if ((tid & 31) == 0) sred[tid >> 5] = ss;
    }
    __syncthreads();
    float d = fmaxf(sqrtf(sred[0] + sred[1]), 1e-12f);
    float r = 1.0f / d;
    float4* o = (float4*)(out + (size_t)n * K_ * C_);
    for (int i = tid; i < K_ * C_ / 4; i += 256) {
        float4 v = o[i];
        o[i] = make_float4(v.x * r, v.y * r, v.z * r, v.w * r);
    }
}

// ============================ launch =========================================
extern "C" void kernel_launch(void* const* d_in, const int* in_sizes, int n_in,
                              void* d_out, int out_size) {
    const float* x    = (const float*)d_in[0];
    const float* w    = (const float*)d_in[1];
    const float* cent = (const float*)d_in[2];
    float* out = (float*)d_out;

    cudaFuncSetAttribute(kFA, cudaFuncAttributeMaxDynamicSharedMemorySize, FA_BYTES);

    kFA<<<dim3(SPLIT, N_), 256, FA_BYTES>>>(x, w);
    kC1<<<dim3(K_, N_), 128>>>(cent, out);
    kC2<<<N_, 256>>>(out);
}